// round 2
// baseline (speedup 1.0000x reference)
#include <cuda_runtime.h>
#include <cuda_bf16.h>

// RelTemporalEncoding: out[n,:] = sum_k wts[k] * (emb[t[n,k]] @ W^T + b)
// Collapsed (exact by linearity):
//   Y = emb @ W^T + b              (3000x62 one-time precompute, ~11.5M FMA)
//   out[n,:] = w0*Y[t0] + w1*Y[t1] + w2*Y[t2]   (gather + weighted sum)
//
// Inputs (metadata order): t int32 [1e6,3], emb f32 [3000,62], W f32 [62,62], b f32 [62]
// Output: f32 [1e6, 62]

#define N_HID   62
#define MAX_LEN 3000
#define Y_PITCH 64   // padded row pitch (floats) -> 256B rows, 32 float2

// Scratch: precomputed Y table (device global; allocation is forbidden)
__device__ float g_Y[MAX_LEN * Y_PITCH];

// ---------------------------------------------------------------------------
// Kernel 1: Y[row][o] = b[o] + sum_d emb[row][d] * W[o][d]
// One block per emb row, 64 threads (62 active). Trivial cost.
// ---------------------------------------------------------------------------
__global__ void precompute_Y(const float* __restrict__ emb,
                             const float* __restrict__ W,
                             const float* __restrict__ b) {
    __shared__ float se[N_HID];
    const int row = blockIdx.x;
    const int o   = threadIdx.x;

    if (o < N_HID) se[o] = emb[row * N_HID + o];
    __syncthreads();

    if (o < N_HID) {
        float acc = b[o];
        const float* wrow = W + o * N_HID;
        #pragma unroll
        for (int d = 0; d < N_HID; ++d) {
            acc = fmaf(se[d], __ldg(&wrow[d]), acc);
        }
        g_Y[row * Y_PITCH + o] = acc;
    }
}

// ---------------------------------------------------------------------------
// Kernel 2: gather + weighted sum; one float2 of output per thread.
// Flat float2 index f: row = f/31, c2 = f%31 (62 floats = 31 float2/row).
// - output stores use .cs (streaming) so the 248MB write stream doesn't
//   evict the 768KB Y table from L2
// - Y reads coalesced within-row; t reads hit <=2 L1 lines per warp
// ---------------------------------------------------------------------------
__global__ void gather_lerp(const int* __restrict__ t,
                            float2* __restrict__ out2,
                            int n_f2) {
    const int f = blockIdx.x * blockDim.x + threadIdx.x;
    if (f >= n_f2) return;

    const unsigned uf  = (unsigned)f;
    const unsigned row = uf / 31u;           // -> mul-hi, cheap
    const unsigned c2  = uf - row * 31u;

    const int t0 = __ldg(&t[row * 3 + 0]);
    const int t1 = __ldg(&t[row * 3 + 1]);
    const int t2 = __ldg(&t[row * 3 + 2]);

    const float2* __restrict__ Y2 = (const float2*)g_Y;  // pitch 32 float2
    const float2 a = __ldg(&Y2[t0 * (Y_PITCH / 2) + c2]);
    const float2 c = __ldg(&Y2[t1 * (Y_PITCH / 2) + c2]);
    const float2 s = __ldg(&Y2[t2 * (Y_PITCH / 2) + c2]);

    const float w0 = 3600.0f / 3661.0f;
    const float w1 = 60.0f   / 3661.0f;
    const float w2 = 1.0f    / 3661.0f;

    float2 r;
    r.x = fmaf(a.x, w0, fmaf(c.x, w1, s.x * w2));
    r.y = fmaf(a.y, w0, fmaf(c.y, w1, s.y * w2));

    __stcs(&out2[f], r);   // streaming store: don't pollute L2
}

// ---------------------------------------------------------------------------
extern "C" void kernel_launch(void* const* d_in, const int* in_sizes, int n_in,
                              void* d_out, int out_size) {
    const int*   t   = (const int*)  d_in[0];
    const float* emb = (const float*)d_in[1];
    const float* W   = (const float*)d_in[2];
    const float* b   = (const float*)d_in[3];
    float2* out2 = (float2*)d_out;

    // Kernel 1: build Y table (3000 rows)
    precompute_Y<<<MAX_LEN, 64>>>(emb, W, b);

    // Kernel 2: gather. out_size floats = out_size/2 float2 elements.
    const int n_f2 = out_size / 2;
    const int threads = 256;
    const int blocks  = (n_f2 + threads - 1) / threads;
    gather_lerp<<<blocks, threads>>>(t, out2, n_f2);
}

// round 3
// speedup vs baseline: 1.1290x; 1.1290x over previous
#include <cuda_runtime.h>
#include <cuda_bf16.h>

// RelTemporalEncoding: out[n,:] = sum_k wts[k] * (emb[t[n,k]] @ W^T + b)
// Collapsed (exact by linearity):
//   Y = emb @ W^T + b              (3000x62 one-time precompute)
//   out[n,:] = w0*Y[t0] + w1*Y[t1] + w2*Y[t2]   (gather + weighted sum)
//
// Inputs: t int32 [1e6,3], emb f32 [3000,62], W f32 [62,62], b f32 [62]
// Output: f32 [1e6, 62]
//
// R2 redesign: float4 Y reads (pitch-64 padding), 2 rows/thread for MLP,
// shared-staged t, streaming stores. Attacks the latency/issue exposure seen
// in R2 ncu (DRAM 24%, L1 53%, issue 31%, regs=16 -> MLP-starved).

#define N_HID   62
#define MAX_LEN 3000
#define Y_PITCH 64            // padded row pitch (floats): 16 aligned float4
#define ROWS_PER_BLOCK 64
#define GL_THREADS 512        // 16 threads/row * 32 rows, x2 row-iterations

// Scratch: precomputed Y table (device global; allocation forbidden)
__device__ float g_Y[MAX_LEN * Y_PITCH];

// ---------------------------------------------------------------------------
// Kernel 1: Y[row][o] = b[o] + sum_d emb[row][d] * W[o][d]
// ---------------------------------------------------------------------------
__global__ void precompute_Y(const float* __restrict__ emb,
                             const float* __restrict__ W,
                             const float* __restrict__ b) {
    __shared__ float se[N_HID];
    const int row = blockIdx.x;
    const int o   = threadIdx.x;

    if (o < N_HID) se[o] = emb[row * N_HID + o];
    __syncthreads();

    if (o < N_HID) {
        float acc = b[o];
        const float* wrow = W + o * N_HID;
        #pragma unroll
        for (int d = 0; d < N_HID; ++d)
            acc = fmaf(se[d], __ldg(&wrow[d]), acc);
        g_Y[row * Y_PITCH + o] = acc;
    }
    // padding floats 62,63 may be read (as dead lanes of a float4) but never
    // used; leave them untouched.
}

// ---------------------------------------------------------------------------
// Kernel 2: gather + weighted sum.
// Block handles 64 consecutive rows. Thread = (row_local, c4), c4 in [0,16):
// reads 3 aligned float4 from Y (pitch 16 float4), writes 2 (or 1) float2.
// Each thread does 2 independent rows -> 6 LDG.128 in flight.
// ---------------------------------------------------------------------------
__global__ __launch_bounds__(GL_THREADS)
void gather_lerp4(const int* __restrict__ t, float* __restrict__ out) {
    __shared__ int ts[ROWS_PER_BLOCK * 3];

    const int tid      = threadIdx.x;
    const int base_row = blockIdx.x * ROWS_PER_BLOCK;

    // Stage this block's 64*3 t-indices (one coalesced load)
    if (tid < ROWS_PER_BLOCK * 3)
        ts[tid] = t[base_row * 3 + tid];
    __syncthreads();

    const int c4  = tid & 15;        // float4 column within row
    const int rl0 = tid >> 4;        // 0..31

    const float4* __restrict__ Y4 = (const float4*)g_Y;  // pitch 16 float4

    const float w0 = 3600.0f / 3661.0f;
    const float w1 = 60.0f   / 3661.0f;
    const float w2 = 1.0f    / 3661.0f;

    #pragma unroll
    for (int it = 0; it < 2; ++it) {
        const int rl = rl0 + it * 32;

        const int t0 = ts[rl * 3 + 0];
        const int t1 = ts[rl * 3 + 1];
        const int t2 = ts[rl * 3 + 2];

        const float4 a = __ldg(&Y4[t0 * (Y_PITCH / 4) + c4]);
        const float4 c = __ldg(&Y4[t1 * (Y_PITCH / 4) + c4]);
        const float4 s = __ldg(&Y4[t2 * (Y_PITCH / 4) + c4]);

        float4 r;
        r.x = fmaf(a.x, w0, fmaf(c.x, w1, s.x * w2));
        r.y = fmaf(a.y, w0, fmaf(c.y, w1, s.y * w2));
        r.z = fmaf(a.z, w0, fmaf(c.z, w1, s.z * w2));
        r.w = fmaf(a.w, w0, fmaf(c.w, w1, s.w * w2));

        // out row is 62 floats (248B): 8B-aligned only -> two STG.64
        float* o = out + (size_t)(base_row + rl) * N_HID + c4 * 4;
        __stcs((float2*)o, make_float2(r.x, r.y));
        if (c4 < 15)                           // c4==15 covers floats 60..61 only
            __stcs((float2*)(o + 2), make_float2(r.z, r.w));
    }
}

// ---------------------------------------------------------------------------
extern "C" void kernel_launch(void* const* d_in, const int* in_sizes, int n_in,
                              void* d_out, int out_size) {
    const int*   t   = (const int*)  d_in[0];
    const float* emb = (const float*)d_in[1];
    const float* W   = (const float*)d_in[2];
    const float* b   = (const float*)d_in[3];
    float* out = (float*)d_out;

    precompute_Y<<<MAX_LEN, 64>>>(emb, W, b);

    const int n_rows = out_size / N_HID;                 // 1,000,000
    const int blocks = (n_rows + ROWS_PER_BLOCK - 1) / ROWS_PER_BLOCK;  // 15625
    gather_lerp4<<<blocks, GL_THREADS>>>(t, out);
}

// round 5
// speedup vs baseline: 1.1317x; 1.0024x over previous
#include <cuda_runtime.h>
#include <cuda_fp16.h>

// RelTemporalEncoding collapsed (exact by linearity):
//   Y = emb @ W^T + b            (3000x62 one-time precompute, fp32 math)
//   out[n,:] = w0*Y[t0] + w1*Y[t1] + w2*Y[t2]
//
// R4 (resubmit; prior round was an infra timeout): Y table stored fp16,
// pitch 64 halves = 128B/row -> each gathered row is ONE L1 line
// (wavefronts 6->3 per row, L2 gather traffic halved). 16 threads/row,
// LDG.64 reads, low regs, full occupancy. Attacks the L1tex-queue bound
// seen in R3 (L1 64.5%, DRAM 35%, occ 86%, issue 25%).
//
// Inputs: t int32 [1e6,3], emb f32 [3000,62], W f32 [62,62], b f32 [62]
// Output: f32 [1e6, 62]

#define N_HID   62
#define MAX_LEN 3000
#define YP      64          // half-pitch: 64 halves = 128 bytes per row
#define GT      512         // gather threads per block
#define RPB     32          // rows per block (16 threads/row)

// fp16 Y table (device global scratch; allocation forbidden)
__device__ __half g_Yh[MAX_LEN * YP];

// ---------------------------------------------------------------------------
// Kernel 1: Y[row][o] = b[o] + sum_d emb[row][d] * W[o][d], stored as fp16.
// Padding cols 62,63 zeroed (loaded by dead lanes but never used).
// ---------------------------------------------------------------------------
__global__ void precompute_Y(const float* __restrict__ emb,
                             const float* __restrict__ W,
                             const float* __restrict__ b) {
    __shared__ float se[N_HID];
    const int row = blockIdx.x;
    const int o   = threadIdx.x;      // 0..63

    if (o < N_HID) se[o] = emb[row * N_HID + o];
    __syncthreads();

    float acc = 0.0f;
    if (o < N_HID) {
        acc = b[o];
        const float* wrow = W + o * N_HID;
        #pragma unroll
        for (int d = 0; d < N_HID; ++d)
            acc = fmaf(se[d], __ldg(&wrow[d]), acc);
    }
    g_Yh[row * YP + o] = __float2half_rn(acc);   // o>=62 writes 0
}

// ---------------------------------------------------------------------------
// Kernel 2: gather + weighted sum.
// 16 threads per row; thread c covers cols [4c, 4c+4). Gather = LDG.64
// (4 halves); one warp's load instruction touches exactly 2 L1 lines
// (one per gathered row). Stores: 2x STG.64 streaming (.cs) so the 248MB
// write stream doesn't evict the 384KB Y table from L2.
// ---------------------------------------------------------------------------
__global__ __launch_bounds__(GT)
void gather_h(const int* __restrict__ t, float* __restrict__ out) {
    __shared__ int ts[RPB * 3];

    const int tid  = threadIdx.x;
    const int base = blockIdx.x * RPB;

    if (tid < RPB * 3)
        ts[tid] = t[base * 3 + tid];
    __syncthreads();

    const int c  = tid & 15;          // column group
    const int rl = tid >> 4;          // local row 0..31

    const int t0 = ts[rl * 3 + 0];
    const int t1 = ts[rl * 3 + 1];
    const int t2 = ts[rl * 3 + 2];

    const float2* __restrict__ Yh = (const float2*)g_Yh;   // 8B = 4 halves; 16/row

    const float2 avb = __ldg(&Yh[t0 * 16 + c]);
    const float2 cvb = __ldg(&Yh[t1 * 16 + c]);
    const float2 svb = __ldg(&Yh[t2 * 16 + c]);

    const __half2* ah = (const __half2*)&avb;
    const __half2* ch = (const __half2*)&cvb;
    const __half2* sh = (const __half2*)&svb;

    const float2 a0 = __half22float2(ah[0]);
    const float2 a1 = __half22float2(ah[1]);
    const float2 c0 = __half22float2(ch[0]);
    const float2 c1 = __half22float2(ch[1]);
    const float2 s0 = __half22float2(sh[0]);
    const float2 s1 = __half22float2(sh[1]);

    const float w0 = 3600.0f / 3661.0f;
    const float w1 = 60.0f   / 3661.0f;
    const float w2 = 1.0f    / 3661.0f;

    float2 r0, r1;
    r0.x = fmaf(a0.x, w0, fmaf(c0.x, w1, s0.x * w2));
    r0.y = fmaf(a0.y, w0, fmaf(c0.y, w1, s0.y * w2));
    r1.x = fmaf(a1.x, w0, fmaf(c1.x, w1, s1.x * w2));
    r1.y = fmaf(a1.y, w0, fmaf(c1.y, w1, s1.y * w2));

    // out row = 62 floats (248B, 8B-aligned). Thread covers cols 4c..4c+3;
    // c==15 covers only cols 60,61 (skip second store).
    float* o = out + (size_t)(base + rl) * N_HID + c * 4;
    __stcs((float2*)o, r0);
    if (c < 15)
        __stcs((float2*)(o + 2), r1);
}

// ---------------------------------------------------------------------------
extern "C" void kernel_launch(void* const* d_in, const int* in_sizes, int n_in,
                              void* d_out, int out_size) {
    const int*   t   = (const int*)  d_in[0];
    const float* emb = (const float*)d_in[1];
    const float* W   = (const float*)d_in[2];
    const float* b   = (const float*)d_in[3];
    float* out = (float*)d_out;

    precompute_Y<<<MAX_LEN, 64>>>(emb, W, b);

    const int n_rows = out_size / N_HID;          // 1,000,000 (divisible by 32)
    const int blocks = n_rows / RPB;              // 31,250
    gather_h<<<blocks, GT>>>(t, out);
}

// round 6
// speedup vs baseline: 1.5315x; 1.3533x over previous
#include <cuda_runtime.h>
#include <cuda_fp16.h>

// RelTemporalEncoding collapsed (exact by linearity):
//   Y = emb @ W^T + b            (3000x62 one-time precompute, fp32 math)
//   out[n,:] = w0*Y[t0] + w1*Y[t1] + w2*Y[t2]
//
// R6: persistent grid-stride gather (no block churn, no barriers), 2 rows
// per thread per iteration -> 6 Y-gathers in flight. fp16 Y table kept
// (128B/row = 1 line/gather). R5 showed all throughput metrics <50% with
// flat time => latency-exposure, not bandwidth, is the bound.
//
// Inputs: t int32 [1e6,3], emb f32 [3000,62], W f32 [62,62], b f32 [62]
// Output: f32 [1e6, 62]

#define N_HID   62
#define MAX_LEN 3000
#define YP      64              // half-pitch: 64 halves = 128B per table row
#define GT      256             // gather threads/block
#define GBLKS   (148 * 8)       // persistent-ish grid

__device__ __half g_Yh[MAX_LEN * YP];

// ---------------------------------------------------------------------------
// Kernel 1: Y = emb @ W^T + b -> fp16. 64 threads (one per output col),
// 4 rows per block: W row loaded once per thread, 4 independent FMA chains.
// ---------------------------------------------------------------------------
#define PR 4
__global__ void precompute_Y(const float* __restrict__ emb,
                             const float* __restrict__ W,
                             const float* __restrict__ b) {
    __shared__ float se[PR][N_HID];
    const int r0 = blockIdx.x * PR;
    const int o  = threadIdx.x;          // 0..63

    // stage 4 emb rows
    for (int i = o; i < PR * N_HID; i += 64)
        se[i / N_HID][i % N_HID] = emb[r0 * N_HID + i];
    __syncthreads();

    float acc0 = 0.f, acc1 = 0.f, acc2 = 0.f, acc3 = 0.f;
    if (o < N_HID) {
        const float* wrow = W + o * N_HID;
        float bb = b[o];
        acc0 = bb; acc1 = bb; acc2 = bb; acc3 = bb;
        #pragma unroll
        for (int d = 0; d < N_HID; ++d) {
            const float w = __ldg(&wrow[d]);
            acc0 = fmaf(se[0][d], w, acc0);
            acc1 = fmaf(se[1][d], w, acc1);
            acc2 = fmaf(se[2][d], w, acc2);
            acc3 = fmaf(se[3][d], w, acc3);
        }
    }
    g_Yh[(r0 + 0) * YP + o] = __float2half_rn(acc0);   // o>=62 -> 0
    g_Yh[(r0 + 1) * YP + o] = __float2half_rn(acc1);
    g_Yh[(r0 + 2) * YP + o] = __float2half_rn(acc2);
    g_Yh[(r0 + 3) * YP + o] = __float2half_rn(acc3);
}

// ---------------------------------------------------------------------------
// Gather core for one row (16 threads/row, thread owns cols 4c..4c+3).
// ---------------------------------------------------------------------------
__device__ __forceinline__ void do_row(const int* __restrict__ t,
                                       const float2* __restrict__ Yh,
                                       float* __restrict__ out,
                                       int row, int c) {
    const int t0 = __ldg(&t[row * 3 + 0]);
    const int t1 = __ldg(&t[row * 3 + 1]);
    const int t2 = __ldg(&t[row * 3 + 2]);

    const float2 av = __ldg(&Yh[t0 * 16 + c]);   // 4 halves
    const float2 cv = __ldg(&Yh[t1 * 16 + c]);
    const float2 sv = __ldg(&Yh[t2 * 16 + c]);

    const __half2* ah = (const __half2*)&av;
    const __half2* ch = (const __half2*)&cv;
    const __half2* sh = (const __half2*)&sv;

    const float2 a0 = __half22float2(ah[0]), a1 = __half22float2(ah[1]);
    const float2 c0 = __half22float2(ch[0]), c1 = __half22float2(ch[1]);
    const float2 s0 = __half22float2(sh[0]), s1 = __half22float2(sh[1]);

    const float w0 = 3600.0f / 3661.0f;
    const float w1 = 60.0f   / 3661.0f;
    const float w2 = 1.0f    / 3661.0f;

    float2 r0, r1;
    r0.x = fmaf(a0.x, w0, fmaf(c0.x, w1, s0.x * w2));
    r0.y = fmaf(a0.y, w0, fmaf(c0.y, w1, s0.y * w2));
    r1.x = fmaf(a1.x, w0, fmaf(c1.x, w1, s1.x * w2));
    r1.y = fmaf(a1.y, w0, fmaf(c1.y, w1, s1.y * w2));

    float* o = out + (size_t)row * N_HID + c * 4;
    __stcs((float2*)o, r0);
    if (c < 15)                          // c==15 covers cols 60..61 only
        __stcs((float2*)(o + 2), r1);
}

// ---------------------------------------------------------------------------
// Kernel 2: persistent grid-stride gather, unroll x2 (2 rows in flight).
// ---------------------------------------------------------------------------
__global__ __launch_bounds__(GT)
void gather_p(const int* __restrict__ t, float* __restrict__ out, int n_rows) {
    const int g = blockIdx.x * GT + threadIdx.x;
    const int c = g & 15;                       // column group (0..15)
    const int stride = (gridDim.x * GT) >> 4;   // row slots in the grid
    int row = g >> 4;

    const float2* __restrict__ Yh = (const float2*)g_Yh;

    // main loop: two independent rows per iteration -> 6 Y-LDGs in flight
    for (; row + stride < n_rows; row += 2 * stride) {
        do_row(t, Yh, out, row,          c);
        do_row(t, Yh, out, row + stride, c);
    }
    if (row < n_rows)
        do_row(t, Yh, out, row, c);
}

// ---------------------------------------------------------------------------
extern "C" void kernel_launch(void* const* d_in, const int* in_sizes, int n_in,
                              void* d_out, int out_size) {
    const int*   t   = (const int*)  d_in[0];
    const float* emb = (const float*)d_in[1];
    const float* W   = (const float*)d_in[2];
    const float* b   = (const float*)d_in[3];
    float* out = (float*)d_out;

    precompute_Y<<<MAX_LEN / PR, 64>>>(emb, W, b);    // 750 blocks

    const int n_rows = out_size / N_HID;              // 1,000,000
    gather_p<<<GBLKS, GT>>>(t, out, n_rows);
}